// round 14
// baseline (speedup 1.0000x reference)
#include <cuda_runtime.h>
#include <cstdint>

// ---------------------------------------------------------------------------
// QLSTM fused persistent kernel, v10 = v9 + de-jammed sync lines + deg-7 sig.
//   * each gate uses only W[0,:]  -> theta is a scalar per batch element
//   * _expval(theta,U) = alpha + R*cos(theta - phi), E in [-1,1]
//   * f,i,g,o scalars per row -> c[b,:], h[b,:] uniform over hidden dim
// Roles (G = 2 x #SM, occ 2):
//   block 0  warps 0-3 : 128 scalar scans, cp.async self-feed (3 bufs ahead)
//            warps 4-7 : help with gate constants, then exit
//   block comp (=#SM)  : exits immediately (shares block 0's SM)
//   other blocks       : chunk-major projection (credits), then chunk-by-
//                        chunk broadcast gated on g_dw (padded, backoff poll)
// Sync words padded to one 128B line each -> no L2 slice jam from pollers.
// ---------------------------------------------------------------------------

#define T_STEPS 256
#define BATCH   128
#define ROWS    (T_STEPS * BATCH)     // 32768
#define DIMQ    256
#define NCH     8
#define CH_T    32                    // scan steps per credit/bcast chunk
#define CHROWS  (CH_T * BATCH)        // 4096 z-rows per chunk
#define REG4    (CHROWS * 128)        // float4 of output per chunk = 524288
#define SEQ_T   8                     // steps per smem buffer
#define NSEQ    (T_STEPS / SEQ_T)     // 32
#define NBUF    4                     // ring depth (4 x 8 x 128 x 16B = 64 KB)
#define PAD     32                    // u32 per 128B line

__device__ float4   g_z[ROWS];        // per (t,b): x-projection per gate
__device__ float    g_h[ROWS];        // h, layout [b][t] (b*256 + t)
__device__ float    g_cfin[BATCH];    // final c per b
__device__ unsigned g_zcnt[NCH * PAD];   // rows done per chunk (idx c*PAD)
__device__ unsigned g_dw[4 * PAD];       // scan chunks done per warp (idx w*PAD)

struct Args {
    const float* x;
    const float* W[4];
    const float* b[4];
    const float* P[4];
    float4* out;
    int G;     // grid size
    int comp;  // companion block id (shares SM with block 0; exits)
    int Wp;    // proj warps = (G-2)*8
    int n4;    // out_size / 4
};

// ---------------- sync primitives ----------------
__device__ __forceinline__ void red_release(unsigned* p, unsigned v) {
    asm volatile("red.release.gpu.add.u32 [%0], %1;" :: "l"(p), "r"(v) : "memory");
}
__device__ __forceinline__ unsigned ld_acq(const unsigned* p) {
    unsigned v;
    asm volatile("ld.acquire.gpu.u32 %0, [%1];" : "=r"(v) : "l"(p) : "memory");
    return v;
}
__device__ __forceinline__ void publish(unsigned* p, unsigned v) {
    asm volatile("fence.acq_rel.gpu;" ::: "memory");
    asm volatile("st.relaxed.gpu.u32 [%0], %1;" :: "l"(p), "r"(v) : "memory");
}
__device__ __forceinline__ void cp_async16(uint32_t dst_smem, const void* src) {
    asm volatile("cp.async.cg.shared.global [%0], [%1], 16;"
                 :: "r"(dst_smem), "l"(src) : "memory");
}
__device__ __forceinline__ void cp_commit() {
    asm volatile("cp.async.commit_group;" ::: "memory");
}
__device__ __forceinline__ void cp_wait2() {
    asm volatile("cp.async.wait_group 2;" ::: "memory");
}

// ---------------- math helpers ----------------
__device__ __forceinline__ float2 cmul(float2 a, float2 b) {
    return make_float2(a.x * b.x - a.y * b.y, a.x * b.y + a.y * b.x);
}
__device__ __forceinline__ int chain_perm(int k) {   // CNOT chain = prefix-XOR
    k ^= k >> 1; k ^= k >> 2; k ^= k >> 4;
    return k & 0xFF;
}
__device__ __forceinline__ float rcpf(float x) {
    float r;
    asm("rcp.approx.f32 %0, %1;" : "=f"(r) : "f"(x));
    return r;
}
__device__ __forceinline__ float ex2f(float x) {
    float r;
    asm("ex2.approx.f32 %0, %1;" : "=f"(r) : "f"(x));
    return r;
}
__device__ __forceinline__ float tanh_hw(float x) {   // ~5e-4 err (feedback only)
    float r;
    asm("tanh.approx.f32 %0, %1;" : "=f"(r) : "f"(x));
    return r;
}
// sigmoid(x), |x|<=1: odd deg-7 Estrin, err ~2e-5, chain 16 after x
__device__ __forceinline__ float sig7(float x) {
    float y  = x * x;
    float a  = fmaf(y, -2.0833333e-2f, 2.5e-1f);          // c1 + c3 y
    float bq = fmaf(y, -2.1084656e-4f, 2.0833333e-3f);    // c5 + c7 y
    float y2 = y * y;
    float p  = fmaf(y2, bq, a);
    return fmaf(x, p, 0.5f);
}

// ---------------- init (reset counters each replay) ----------------
__global__ void init_kernel() {
    int i = threadIdx.x;
    if (i < NCH) g_zcnt[i * PAD] = 0u;
    if (i < 4)  g_dw[i * PAD]   = 0u;
}

// ---------------- fused kernel ----------------
__global__ void __launch_bounds__(256, 2) fused_kernel(Args a) {
    extern __shared__ float4 s_z[];   // [NBUF][SEQ_T][BATCH] = 64 KB (block 0 only)

    const int bid  = blockIdx.x;
    const int tid  = threadIdx.x;
    const int warp = tid >> 5, lane = tid & 31;

    if (bid == a.comp) return;        // vacate block 0's SM

    // ============================ block 0: consts + lean scan ============================
    if (bid == 0) {
        __shared__ float2 rot[2][8][2][2];
        __shared__ float2 u0[DIMQ];
        __shared__ float2 u1[DIMQ];
        __shared__ float  rbuf[4][8];
        __shared__ float  s_gate[4][5];        // alpha, R, phi, sW, b0

        const int k   = tid;
        const int pk0 = chain_perm(k);

        // -------- gate constants (all 256 threads, 4 gates) --------
        for (int g = 0; g < 4; ++g) {
            __syncthreads();
            const float* P = a.P[g];
            if (k < 16) {
                int l = k >> 3, w = k & 7;
                float phi = P[(l * 8 + w) * 3 + 0];
                float th  = P[(l * 8 + w) * 3 + 1];
                float om  = P[(l * 8 + w) * 3 + 2];
                float s, c;
                __sincosf(0.5f * th, &s, &c);
                float hp = 0.5f * (phi + om);
                float hm = 0.5f * (phi - om);
                float2 ep = make_float2(__cosf(hp), -__sinf(hp));
                float2 em = make_float2(__cosf(hm),  __sinf(hm));
                rot[l][w][0][0] = make_float2( ep.x * c,  ep.y * c);
                rot[l][w][0][1] = make_float2(-em.x * s, -em.y * s);
                rot[l][w][1][0] = make_float2( em.x * s, -em.y * s);
                rot[l][w][1][1] = make_float2( ep.x * c, -ep.y * c);
            }
            __syncthreads();

            float2 a0v = make_float2(1.f, 0.f);
            float2 a1v = make_float2(1.f, 0.f);
            #pragma unroll
            for (int w = 0; w < 8; ++w) {
                int kb = (k >> (7 - w)) & 1;
                a0v = cmul(a0v, rot[0][w][kb][0]);
                a1v = cmul(a1v, rot[0][w][kb][(w == 0) ? 1 : 0]);
            }
            u0[pk0] = a0v;
            u1[pk0] = a1v;
            __syncthreads();

            #pragma unroll
            for (int w = 0; w < 8; ++w) {
                int p = 7 - w, m = 1 << p, kb = (k >> p) & 1;
                float2 x0 = u0[k & ~m], x1 = u0[k | m];
                float2 y0 = u1[k & ~m], y1 = u1[k | m];
                __syncthreads();
                float2 r0 = rot[1][w][kb][0];
                float2 r1 = rot[1][w][kb][1];
                u0[k] = make_float2(r0.x * x0.x - r0.y * x0.y + r1.x * x1.x - r1.y * x1.y,
                                    r0.x * x0.y + r0.y * x0.x + r1.x * x1.y + r1.y * x1.x);
                u1[k] = make_float2(r0.x * y0.x - r0.y * y0.y + r1.x * y1.x - r1.y * y1.y,
                                    r0.x * y0.y + r0.y * y0.x + r1.x * y1.y + r1.y * y1.x);
                __syncthreads();
            }

            float2 c0 = u0[k], c1 = u1[k];
            __syncthreads();
            u0[pk0] = c0; u1[pk0] = c1;
            __syncthreads();
            c0 = u0[k]; c1 = u1[k];

            float z0 = (k < 128) ? 1.f : -1.f;
            float A  = z0 * (c0.x * c0.x + c0.y * c0.y);
            float Bv = z0 * (c1.x * c1.x + c1.y * c1.y);
            float Cv = -2.f * z0 * (c0.y * c1.x - c0.x * c1.y);
            const float* W = a.W[g];
            float sw = W[512 + k] + W[768 + k];

            float vals[4] = {A, Bv, Cv, sw};
            #pragma unroll
            for (int i = 0; i < 4; ++i) {
                float xv = vals[i];
                #pragma unroll
                for (int off = 16; off; off >>= 1)
                    xv += __shfl_xor_sync(0xffffffffu, xv, off);
                if (lane == 0) rbuf[i][warp] = xv;
            }
            __syncthreads();
            if (k == 0) {
                float t[4];
                #pragma unroll
                for (int i = 0; i < 4; ++i) {
                    float s = 0.f;
                    #pragma unroll
                    for (int wv = 0; wv < 8; ++wv) s += rbuf[i][wv];
                    t[i] = s;
                }
                float alpha = 0.5f * (t[0] + t[1]);
                float beta  = 0.5f * (t[0] - t[1]);
                float gamma = 0.5f * t[2];
                float R     = sqrtf(beta * beta + gamma * gamma);
                float phi   = (R > 0.f) ? atan2f(gamma, beta) : 0.f;
                s_gate[g][0] = alpha;
                s_gate[g][1] = R;
                s_gate[g][2] = phi;
                s_gate[g][3] = t[3];
                s_gate[g][4] = a.b[g][0];
            }
        }
        __syncthreads();

        if (tid >= BATCH) return;   // warps 4-7 exit: scan SM stays quiet

        // ========== warps 0-3: lean self-feeding scalar scan ==========
        const int b = tid;
        const float af = s_gate[0][0], Rf = s_gate[0][1], swf = s_gate[0][3];
        const float ai = s_gate[1][0], Ri = s_gate[1][1], swi = s_gate[1][3];
        const float ag = s_gate[2][0], Rg = s_gate[2][1], swg = s_gate[2][3];
        const float ao = s_gate[3][0], Ro = s_gate[3][1], swo = s_gate[3][3];
        const float tbf = s_gate[0][4] - s_gate[0][2];
        const float tbi = s_gate[1][4] - s_gate[1][2];
        const float tbg = s_gate[2][4] - s_gate[2][2];
        const float tbo = s_gate[3][4] - s_gate[3][2];

        const uint32_t smem_base =
            (uint32_t)__cvta_generic_to_shared(s_z) + (uint32_t)b * 16u;
        #define SLOT_ADDR(slot, s) (smem_base + ((uint32_t)(slot) * SEQ_T + (uint32_t)(s)) * (BATCH * 16u))

        // prologue: wait chunk 0 credit, issue buffers 0..2
        if (lane == 0) { while (ld_acq(&g_zcnt[0]) < (unsigned)CHROWS) {} }
        __syncwarp();
        #pragma unroll
        for (int q = 0; q < 3; ++q) {
            #pragma unroll
            for (int s = 0; s < SEQ_T; ++s)
                cp_async16(SLOT_ADDR(q & (NBUF - 1), s), &g_z[(q * SEQ_T + s) * BATCH + b]);
            cp_commit();
        }

        float h = 0.f, cc = 0.f;
        float hbuf[SEQ_T];

        // lean step: feedback h via HW tanh.approx; stored h accurate (off-chain);
        // gate i folded into g's Pade numerator; deg-7 Estrin sigmoids.
        #define QSTEP(ZV, S) { \
            float thf = fmaf(h, swf, (ZV).x); \
            float thi = fmaf(h, swi, (ZV).y); \
            float thg = fmaf(h, swg, (ZV).z); \
            float tho = fmaf(h, swo, (ZV).w); \
            float Ef = fmaf(Rf, __cosf(thf), af); \
            float Ei = fmaf(Ri, __cosf(thi), ai); \
            float Eg = fmaf(Rg, __cosf(thg), ag); \
            float Eo = fmaf(Ro, __cosf(tho), ao); \
            float ff = sig7(Ef); \
            float ii = sig7(Ei); \
            float oo = sig7(Eo); \
            float y  = Eg * Eg; \
            float t1 = fmaf(y, 4725.f, 10395.f); \
            float y2 = y * y; \
            float d  = fmaf(y2, y + 210.f, t1); \
            float n  = fmaf(y, fmaf(y, 21.f, 1260.f), 10395.f); \
            float xni = Eg * n * ii; \
            float p  = ff * cc; \
            cc = fmaf(xni, rcpf(d), p); \
            h  = oo * tanh_hw(cc); \
            float es = ex2f(cc * 2.8853900817779268f); \
            hbuf[S] = oo * fmaf(-2.f, rcpf(es + 1.f), 1.f); \
        }

        for (int seq = 0; seq < NSEQ; ++seq) {
            cp_wait2();   // buffer `seq` complete (<=2 groups pending)

            const float4* src = &s_z[(size_t)(seq & (NBUF - 1)) * SEQ_T * BATCH + b];
            float4 zv[SEQ_T];
            #pragma unroll
            for (int s = 0; s < SEQ_T; ++s) {
                float4 z = src[s * BATCH];
                zv[s] = make_float4(z.x + tbf, z.y + tbi, z.z + tbg, z.w + tbo);
            }

            const int nx = seq + 3;
            if (nx < NSEQ) {
                if ((nx & 3) == 0) {   // new credit chunk; almost always ready
                    const int c = nx >> 2;
                    if (lane == 0) { while (ld_acq(&g_zcnt[c * PAD]) < (unsigned)CHROWS) {} }
                    __syncwarp();
                }
                #pragma unroll
                for (int s = 0; s < SEQ_T; ++s)
                    cp_async16(SLOT_ADDR(nx & (NBUF - 1), s), &g_z[(nx * SEQ_T + s) * BATCH + b]);
            }
            cp_commit();   // uniform group count

            #pragma unroll
            for (int s = 0; s < SEQ_T; ++s) QSTEP(zv[s], s);

            // flush 8 h values: two STG.128 (g_h layout [b][t])
            {
                float4* hdst = reinterpret_cast<float4*>(&g_h[b * T_STEPS + seq * SEQ_T]);
                hdst[0] = make_float4(hbuf[0], hbuf[1], hbuf[2], hbuf[3]);
                hdst[1] = make_float4(hbuf[4], hbuf[5], hbuf[6], hbuf[7]);
            }

            if ((seq & 3) == 3) {
                __syncwarp();
                if (lane == 0) publish(&g_dw[warp * PAD], (unsigned)((seq >> 2) + 1));
            }
        }
        #undef QSTEP
        #undef SLOT_ADDR
        g_cfin[b] = cc;
        __syncwarp();
        if (lane == 0) publish(&g_dw[warp * PAD], 8u);   // idempotent final publish
        return;
    }

    // ============================ workers ============================
    const int wr = bid - 1 - (bid > a.comp ? 1 : 0);

    // -------- PHASE 1: projection, CHUNK-MAJOR order + credits --------
    {
        const int gw = wr * 8 + warp;   // 0 .. Wp-1
        const float4* x4 = reinterpret_cast<const float4*>(a.x);

        float4 wv0[4], wv1[4], wv2[4], wv3[4];
        {
            const float4* W0 = reinterpret_cast<const float4*>(a.W[0]);
            const float4* W1 = reinterpret_cast<const float4*>(a.W[1]);
            const float4* W2 = reinterpret_cast<const float4*>(a.W[2]);
            const float4* W3 = reinterpret_cast<const float4*>(a.W[3]);
            #pragma unroll
            for (int it = 0; it < 4; ++it) {
                int e4 = it * 32 + lane;
                wv0[it] = W0[e4]; wv1[it] = W1[e4];
                wv2[it] = W2[e4]; wv3[it] = W3[e4];
            }
        }

        for (int c = 0; c < NCH; ++c) {
            const int cbase = c * CHROWS;
            int done = 0;
            for (int r = cbase + gw; r < cbase + CHROWS; r += a.Wp) {
                const float4* xr = x4 + (size_t)r * 128;
                float s0 = 0.f, s1 = 0.f, s2 = 0.f, s3 = 0.f;
                #pragma unroll
                for (int it = 0; it < 4; ++it) {
                    float4 xv = xr[it * 32 + lane];
                    s0 = fmaf(xv.x, wv0[it].x, s0); s0 = fmaf(xv.y, wv0[it].y, s0);
                    s0 = fmaf(xv.z, wv0[it].z, s0); s0 = fmaf(xv.w, wv0[it].w, s0);
                    s1 = fmaf(xv.x, wv1[it].x, s1); s1 = fmaf(xv.y, wv1[it].y, s1);
                    s1 = fmaf(xv.z, wv1[it].z, s1); s1 = fmaf(xv.w, wv1[it].w, s1);
                    s2 = fmaf(xv.x, wv2[it].x, s2); s2 = fmaf(xv.y, wv2[it].y, s2);
                    s2 = fmaf(xv.z, wv2[it].z, s2); s2 = fmaf(xv.w, wv2[it].w, s2);
                    s3 = fmaf(xv.x, wv3[it].x, s3); s3 = fmaf(xv.y, wv3[it].y, s3);
                    s3 = fmaf(xv.z, wv3[it].z, s3); s3 = fmaf(xv.w, wv3[it].w, s3);
                }
                #pragma unroll
                for (int off = 16; off; off >>= 1) {
                    s0 += __shfl_xor_sync(0xffffffffu, s0, off);
                    s1 += __shfl_xor_sync(0xffffffffu, s1, off);
                    s2 += __shfl_xor_sync(0xffffffffu, s2, off);
                    s3 += __shfl_xor_sync(0xffffffffu, s3, off);
                }
                if (lane == 0) g_z[r] = make_float4(s0, s1, s2, s3);
                ++done;
            }
            if (lane == 0 && done) red_release(&g_zcnt[c * PAD], (unsigned)done);
        }
    }

    // -------- PHASE 2: broadcast, chunk-by-chunk gated on padded g_dw --------
    {
        float4* out = a.out;
        const int stride = (a.G - 2) * 256;
        const int self   = wr * 256 + tid;

        for (int c = 0; c < NCH; ++c) {
            if (tid == 0) {
                while (ld_acq(&g_dw[0 * PAD]) < (unsigned)(c + 1) ||
                       ld_acq(&g_dw[1 * PAD]) < (unsigned)(c + 1) ||
                       ld_acq(&g_dw[2 * PAD]) < (unsigned)(c + 1) ||
                       ld_acq(&g_dw[3 * PAD]) < (unsigned)(c + 1)) __nanosleep(512);
            }
            __syncthreads();
            const int base = c * REG4;
            const int end  = base + REG4;
            #pragma unroll 2
            for (int i = base + self; i < end; i += stride) {
                int row = i >> 7;                       // row = t*128 + b
                float v = g_h[((row & 127) << 8) | (row >> 7)];   // [b][t]
                out[i] = make_float4(v, v, v, v);
            }
        }
        // hx + cx
        const int base = NCH * REG4;   // == ROWS*128
        for (int i = base + self; i < a.n4; i += stride) {
            int row = i >> 7;
            float v;
            if (row < ROWS + BATCH) v = g_h[((row - ROWS) << 8) | 255]; // hx = h[b][255]
            else                    v = g_cfin[row - ROWS - BATCH];     // cx
            out[i] = make_float4(v, v, v, v);
        }
    }
}

// ---------------- launch ----------------
extern "C" void kernel_launch(void* const* d_in, const int* in_sizes, int n_in,
                              void* d_out, int out_size) {
    static int s_sm = -1;
    const int DYN = NBUF * SEQ_T * BATCH * (int)sizeof(float4);   // 64 KB
    if (s_sm < 0) {
        int dev = 0;
        cudaGetDevice(&dev);
        cudaDeviceGetAttribute(&s_sm, cudaDevAttrMultiProcessorCount, dev);
        if (s_sm <= 0) s_sm = 148;
        cudaFuncSetAttribute(fused_kernel,
                             cudaFuncAttributeMaxDynamicSharedMemorySize, DYN);
    }
    const int G    = 2 * s_sm;
    const int comp = s_sm;              // companion of block 0 (classic placement)
    const int Wp   = (G - 2) * 8;

    Args a;
    a.x = (const float*)d_in[0];
    a.W[0] = (const float*)d_in[1];  a.b[0] = (const float*)d_in[2];  a.P[0] = (const float*)d_in[3];
    a.W[1] = (const float*)d_in[4];  a.b[1] = (const float*)d_in[5];  a.P[1] = (const float*)d_in[6];
    a.W[2] = (const float*)d_in[7];  a.b[2] = (const float*)d_in[8];  a.P[2] = (const float*)d_in[9];
    a.W[3] = (const float*)d_in[10]; a.b[3] = (const float*)d_in[11]; a.P[3] = (const float*)d_in[12];
    a.out  = (float4*)d_out;
    a.G    = G;
    a.comp = comp;
    a.Wp   = Wp;
    a.n4   = out_size / 4;

    init_kernel<<<1, 32>>>();
    fused_kernel<<<G, 256, DYN>>>(a);
}

// round 15
// speedup vs baseline: 1.1152x; 1.1152x over previous
#include <cuda_runtime.h>
#include <cstdint>

// ---------------------------------------------------------------------------
// QLSTM fused persistent kernel, v11 = v9(R13) + RUNTIME smid-based vacate.
//   * each gate uses only W[0,:]  -> theta is a scalar per batch element
//   * _expval(theta,U) = alpha + R*cos(theta - phi), E in [-1,1]
//   * f,i,g,o scalars per row -> c[b,:], h[b,:] uniform over hidden dim
// Roles (G = 2 x #SM, occ 2, all resident):
//   block 0  warps 0-3 : 128 scalar scans, cp.async self-feed (3 bufs ahead)
//            warps 4-7 : help with gate constants, then exit
//   the ONE worker block whose %smid == block 0's %smid exits immediately
//     (runtime-detected; no placement-LUT assumption) -> scan SM exclusive
//   other blocks       : dense rank via atomic ticket; chunk-major projection
//                        (credits), then chunk-by-chunk broadcast on g_dw
// ---------------------------------------------------------------------------

#define T_STEPS 256
#define BATCH   128
#define ROWS    (T_STEPS * BATCH)     // 32768
#define DIMQ    256
#define NCH     8
#define CH_T    32                    // scan steps per credit/bcast chunk
#define CHROWS  (CH_T * BATCH)        // 4096 z-rows per chunk
#define REG4    (CHROWS * 128)        // float4 of output per chunk = 524288
#define SEQ_T   8                     // steps per smem buffer
#define NSEQ    (T_STEPS / SEQ_T)     // 32
#define NBUF    4                     // ring depth (4 x 8 x 128 x 16B = 64 KB)

__device__ float4   g_z[ROWS];        // per (t,b): x-projection per gate
__device__ float    g_h[ROWS];        // h, layout [b][t] (b*256 + t)
__device__ float    g_cfin[BATCH];    // final c per b
__device__ unsigned g_zcnt[NCH];      // z rows completed per chunk (target 4096)
__device__ unsigned g_dw[4];          // scan chunks completed per scan warp
__device__ unsigned g_b0smid;         // block 0's smid | 0x80000000
__device__ unsigned g_wrank;          // worker rank ticket

struct Args {
    const float* x;
    const float* W[4];
    const float* b[4];
    const float* P[4];
    float4* out;
    int G;     // grid size
    int Wp;    // proj warps = (G-2)*8
    int n4;    // out_size / 4
};

// ---------------- sync primitives ----------------
__device__ __forceinline__ void red_release(unsigned* p, unsigned v) {
    asm volatile("red.release.gpu.add.u32 [%0], %1;" :: "l"(p), "r"(v) : "memory");
}
__device__ __forceinline__ unsigned ld_acq(const unsigned* p) {
    unsigned v;
    asm volatile("ld.acquire.gpu.u32 %0, [%1];" : "=r"(v) : "l"(p) : "memory");
    return v;
}
__device__ __forceinline__ void publish(unsigned* p, unsigned v) {
    asm volatile("fence.acq_rel.gpu;" ::: "memory");
    asm volatile("st.relaxed.gpu.u32 [%0], %1;" :: "l"(p), "r"(v) : "memory");
}
__device__ __forceinline__ void cp_async16(uint32_t dst_smem, const void* src) {
    asm volatile("cp.async.cg.shared.global [%0], [%1], 16;"
                 :: "r"(dst_smem), "l"(src) : "memory");
}
__device__ __forceinline__ void cp_commit() {
    asm volatile("cp.async.commit_group;" ::: "memory");
}
__device__ __forceinline__ void cp_wait2() {
    asm volatile("cp.async.wait_group 2;" ::: "memory");
}
__device__ __forceinline__ unsigned smid() {
    unsigned r;
    asm("mov.u32 %0, %%smid;" : "=r"(r));
    return r;
}

// ---------------- math helpers ----------------
__device__ __forceinline__ float2 cmul(float2 a, float2 b) {
    return make_float2(a.x * b.x - a.y * b.y, a.x * b.y + a.y * b.x);
}
__device__ __forceinline__ int chain_perm(int k) {   // CNOT chain = prefix-XOR
    k ^= k >> 1; k ^= k >> 2; k ^= k >> 4;
    return k & 0xFF;
}
__device__ __forceinline__ float rcpf(float x) {
    float r;
    asm("rcp.approx.f32 %0, %1;" : "=f"(r) : "f"(x));
    return r;
}
__device__ __forceinline__ float ex2f(float x) {
    float r;
    asm("ex2.approx.f32 %0, %1;" : "=f"(r) : "f"(x));
    return r;
}
__device__ __forceinline__ float tanh_hw(float x) {   // ~5e-4 err (feedback only)
    float r;
    asm("tanh.approx.f32 %0, %1;" : "=f"(r) : "f"(x));
    return r;
}
// sigmoid(x), |x|<=1: odd Taylor deg 9, err <= 2.2e-6
__device__ __forceinline__ float sig_poly(float x) {
    float y = x * x;
    float p = fmaf(y,  2.1356999e-5f, -2.1084600e-4f);
    p = fmaf(y, p,  2.0833333e-3f);
    p = fmaf(y, p, -2.0833333e-2f);
    p = fmaf(y, p,  2.5e-1f);
    return fmaf(x, p, 0.5f);
}

// ---------------- init (reset counters each replay) ----------------
__global__ void init_kernel() {
    int i = threadIdx.x;
    if (i < NCH) g_zcnt[i] = 0u;
    if (i < 4)  g_dw[i]   = 0u;
    if (i == 4) g_b0smid  = 0u;
    if (i == 5) g_wrank   = 0u;
}

// ---------------- fused kernel ----------------
__global__ void __launch_bounds__(256, 2) fused_kernel(Args a) {
    extern __shared__ float4 s_z[];   // [NBUF][SEQ_T][BATCH] = 64 KB (block 0 only)

    const int bid  = blockIdx.x;
    const int tid  = threadIdx.x;
    const int warp = tid >> 5, lane = tid & 31;

    // ============================ block 0: consts + lean scan ============================
    if (bid == 0) {
        if (tid == 0) publish(&g_b0smid, smid() | 0x80000000u);   // announce my SM

        __shared__ float2 rot[2][8][2][2];
        __shared__ float2 u0[DIMQ];
        __shared__ float2 u1[DIMQ];
        __shared__ float  rbuf[4][8];
        __shared__ float  s_gate[4][5];        // alpha, R, phi, sW, b0

        const int k   = tid;
        const int pk0 = chain_perm(k);

        // -------- gate constants (all 256 threads, 4 gates) --------
        for (int g = 0; g < 4; ++g) {
            __syncthreads();
            const float* P = a.P[g];
            if (k < 16) {
                int l = k >> 3, w = k & 7;
                float phi = P[(l * 8 + w) * 3 + 0];
                float th  = P[(l * 8 + w) * 3 + 1];
                float om  = P[(l * 8 + w) * 3 + 2];
                float s, c;
                __sincosf(0.5f * th, &s, &c);
                float hp = 0.5f * (phi + om);
                float hm = 0.5f * (phi - om);
                float2 ep = make_float2(__cosf(hp), -__sinf(hp));
                float2 em = make_float2(__cosf(hm),  __sinf(hm));
                rot[l][w][0][0] = make_float2( ep.x * c,  ep.y * c);
                rot[l][w][0][1] = make_float2(-em.x * s, -em.y * s);
                rot[l][w][1][0] = make_float2( em.x * s, -em.y * s);
                rot[l][w][1][1] = make_float2( ep.x * c, -ep.y * c);
            }
            __syncthreads();

            float2 a0v = make_float2(1.f, 0.f);
            float2 a1v = make_float2(1.f, 0.f);
            #pragma unroll
            for (int w = 0; w < 8; ++w) {
                int kb = (k >> (7 - w)) & 1;
                a0v = cmul(a0v, rot[0][w][kb][0]);
                a1v = cmul(a1v, rot[0][w][kb][(w == 0) ? 1 : 0]);
            }
            u0[pk0] = a0v;
            u1[pk0] = a1v;
            __syncthreads();

            #pragma unroll
            for (int w = 0; w < 8; ++w) {
                int p = 7 - w, m = 1 << p, kb = (k >> p) & 1;
                float2 x0 = u0[k & ~m], x1 = u0[k | m];
                float2 y0 = u1[k & ~m], y1 = u1[k | m];
                __syncthreads();
                float2 r0 = rot[1][w][kb][0];
                float2 r1 = rot[1][w][kb][1];
                u0[k] = make_float2(r0.x * x0.x - r0.y * x0.y + r1.x * x1.x - r1.y * x1.y,
                                    r0.x * x0.y + r0.y * x0.x + r1.x * x1.y + r1.y * x1.x);
                u1[k] = make_float2(r0.x * y0.x - r0.y * y0.y + r1.x * y1.x - r1.y * y1.y,
                                    r0.x * y0.y + r0.y * y0.x + r1.x * y1.y + r1.y * y1.x);
                __syncthreads();
            }

            float2 c0 = u0[k], c1 = u1[k];
            __syncthreads();
            u0[pk0] = c0; u1[pk0] = c1;
            __syncthreads();
            c0 = u0[k]; c1 = u1[k];

            float z0 = (k < 128) ? 1.f : -1.f;
            float A  = z0 * (c0.x * c0.x + c0.y * c0.y);
            float Bv = z0 * (c1.x * c1.x + c1.y * c1.y);
            float Cv = -2.f * z0 * (c0.y * c1.x - c0.x * c1.y);
            const float* W = a.W[g];
            float sw = W[512 + k] + W[768 + k];

            float vals[4] = {A, Bv, Cv, sw};
            #pragma unroll
            for (int i = 0; i < 4; ++i) {
                float xv = vals[i];
                #pragma unroll
                for (int off = 16; off; off >>= 1)
                    xv += __shfl_xor_sync(0xffffffffu, xv, off);
                if (lane == 0) rbuf[i][warp] = xv;
            }
            __syncthreads();
            if (k == 0) {
                float t[4];
                #pragma unroll
                for (int i = 0; i < 4; ++i) {
                    float s = 0.f;
                    #pragma unroll
                    for (int wv = 0; wv < 8; ++wv) s += rbuf[i][wv];
                    t[i] = s;
                }
                float alpha = 0.5f * (t[0] + t[1]);
                float beta  = 0.5f * (t[0] - t[1]);
                float gamma = 0.5f * t[2];
                float R     = sqrtf(beta * beta + gamma * gamma);
                float phi   = (R > 0.f) ? atan2f(gamma, beta) : 0.f;
                s_gate[g][0] = alpha;
                s_gate[g][1] = R;
                s_gate[g][2] = phi;
                s_gate[g][3] = t[3];
                s_gate[g][4] = a.b[g][0];
            }
        }
        __syncthreads();

        if (tid >= BATCH) return;   // warps 4-7 exit: scan SM stays quiet

        // ========== warps 0-3: lean self-feeding scalar scan ==========
        const int b = tid;
        const float af = s_gate[0][0], Rf = s_gate[0][1], swf = s_gate[0][3];
        const float ai = s_gate[1][0], Ri = s_gate[1][1], swi = s_gate[1][3];
        const float ag = s_gate[2][0], Rg = s_gate[2][1], swg = s_gate[2][3];
        const float ao = s_gate[3][0], Ro = s_gate[3][1], swo = s_gate[3][3];
        const float tbf = s_gate[0][4] - s_gate[0][2];
        const float tbi = s_gate[1][4] - s_gate[1][2];
        const float tbg = s_gate[2][4] - s_gate[2][2];
        const float tbo = s_gate[3][4] - s_gate[3][2];

        const uint32_t smem_base =
            (uint32_t)__cvta_generic_to_shared(s_z) + (uint32_t)b * 16u;
        #define SLOT_ADDR(slot, s) (smem_base + ((uint32_t)(slot) * SEQ_T + (uint32_t)(s)) * (BATCH * 16u))

        // prologue: wait chunk 0 credit, issue buffers 0..2
        if (lane == 0) { while (ld_acq(&g_zcnt[0]) < (unsigned)CHROWS) {} }
        __syncwarp();
        #pragma unroll
        for (int q = 0; q < 3; ++q) {
            #pragma unroll
            for (int s = 0; s < SEQ_T; ++s)
                cp_async16(SLOT_ADDR(q & (NBUF - 1), s), &g_z[(q * SEQ_T + s) * BATCH + b]);
            cp_commit();
        }

        float h = 0.f, cc = 0.f;
        float hbuf[SEQ_T];

        #define QSTEP(ZV, S) { \
            float thf = fmaf(h, swf, (ZV).x); \
            float thi = fmaf(h, swi, (ZV).y); \
            float thg = fmaf(h, swg, (ZV).z); \
            float tho = fmaf(h, swo, (ZV).w); \
            float Ef = fmaf(Rf, __cosf(thf), af); \
            float Ei = fmaf(Ri, __cosf(thi), ai); \
            float Eg = fmaf(Rg, __cosf(thg), ag); \
            float Eo = fmaf(Ro, __cosf(tho), ao); \
            float ff = sig_poly(Ef); \
            float ii = sig_poly(Ei); \
            float oo = sig_poly(Eo); \
            float y  = Eg * Eg; \
            float t1 = fmaf(y, 4725.f, 10395.f); \
            float y2 = y * y; \
            float d  = fmaf(y2, y + 210.f, t1); \
            float n  = fmaf(y, fmaf(y, 21.f, 1260.f), 10395.f); \
            float xni = Eg * n * ii; \
            float p  = ff * cc; \
            cc = fmaf(xni, rcpf(d), p); \
            h  = oo * tanh_hw(cc); \
            float es = ex2f(cc * 2.8853900817779268f); \
            hbuf[S] = oo * fmaf(-2.f, rcpf(es + 1.f), 1.f); \
        }

        for (int seq = 0; seq < NSEQ; ++seq) {
            cp_wait2();   // buffer `seq` complete (<=2 groups pending)

            const float4* src = &s_z[(size_t)(seq & (NBUF - 1)) * SEQ_T * BATCH + b];
            float4 zv[SEQ_T];
            #pragma unroll
            for (int s = 0; s < SEQ_T; ++s) {
                float4 z = src[s * BATCH];
                zv[s] = make_float4(z.x + tbf, z.y + tbi, z.z + tbg, z.w + tbo);
            }

            const int nx = seq + 3;
            if (nx < NSEQ) {
                if ((nx & 3) == 0) {   // new credit chunk; almost always ready
                    const int c = nx >> 2;
                    if (lane == 0) { while (ld_acq(&g_zcnt[c]) < (unsigned)CHROWS) {} }
                    __syncwarp();
                }
                #pragma unroll
                for (int s = 0; s < SEQ_T; ++s)
                    cp_async16(SLOT_ADDR(nx & (NBUF - 1), s), &g_z[(nx * SEQ_T + s) * BATCH + b]);
            }
            cp_commit();   // uniform group count

            #pragma unroll
            for (int s = 0; s < SEQ_T; ++s) QSTEP(zv[s], s);

            // flush 8 h values: two STG.128 (g_h layout [b][t])
            {
                float4* hdst = reinterpret_cast<float4*>(&g_h[b * T_STEPS + seq * SEQ_T]);
                hdst[0] = make_float4(hbuf[0], hbuf[1], hbuf[2], hbuf[3]);
                hdst[1] = make_float4(hbuf[4], hbuf[5], hbuf[6], hbuf[7]);
            }

            if ((seq & 3) == 3) {
                __syncwarp();
                if (lane == 0) publish(&g_dw[warp], (unsigned)((seq >> 2) + 1));
            }
        }
        #undef QSTEP
        #undef SLOT_ADDR
        g_cfin[b] = cc;
        __syncwarp();
        if (lane == 0) publish(&g_dw[warp], 8u);   // idempotent final publish
        return;
    }

    // ============================ workers ============================
    // runtime vacate: the one block sharing block 0's SM exits; others take
    // dense ranks via atomic ticket (no placement assumptions).
    __shared__ int s_wr;
    {
        if (tid == 0) {
            unsigned b0;
            while (((b0 = ld_acq(&g_b0smid)) & 0x80000000u) == 0u) {}
            if ((b0 & 0x7FFFFFFFu) == smid()) {
                s_wr = -1;                                   // I'm the sibling: vacate
            } else {
                s_wr = (int)atomicAdd(&g_wrank, 1u);         // dense worker rank
            }
        }
        __syncthreads();
        if (s_wr < 0) return;
    }
    const int wr = s_wr;

    // -------- PHASE 1: projection, CHUNK-MAJOR order + credits --------
    {
        const int gw = wr * 8 + warp;   // 0 .. Wp-1
        const float4* x4 = reinterpret_cast<const float4*>(a.x);

        float4 wv0[4], wv1[4], wv2[4], wv3[4];
        {
            const float4* W0 = reinterpret_cast<const float4*>(a.W[0]);
            const float4* W1 = reinterpret_cast<const float4*>(a.W[1]);
            const float4* W2 = reinterpret_cast<const float4*>(a.W[2]);
            const float4* W3 = reinterpret_cast<const float4*>(a.W[3]);
            #pragma unroll
            for (int it = 0; it < 4; ++it) {
                int e4 = it * 32 + lane;
                wv0[it] = W0[e4]; wv1[it] = W1[e4];
                wv2[it] = W2[e4]; wv3[it] = W3[e4];
            }
        }

        for (int c = 0; c < NCH; ++c) {
            const int cbase = c * CHROWS;
            int done = 0;
            for (int r = cbase + gw; r < cbase + CHROWS; r += a.Wp) {
                const float4* xr = x4 + (size_t)r * 128;
                float s0 = 0.f, s1 = 0.f, s2 = 0.f, s3 = 0.f;
                #pragma unroll
                for (int it = 0; it < 4; ++it) {
                    float4 xv = xr[it * 32 + lane];
                    s0 = fmaf(xv.x, wv0[it].x, s0); s0 = fmaf(xv.y, wv0[it].y, s0);
                    s0 = fmaf(xv.z, wv0[it].z, s0); s0 = fmaf(xv.w, wv0[it].w, s0);
                    s1 = fmaf(xv.x, wv1[it].x, s1); s1 = fmaf(xv.y, wv1[it].y, s1);
                    s1 = fmaf(xv.z, wv1[it].z, s1); s1 = fmaf(xv.w, wv1[it].w, s1);
                    s2 = fmaf(xv.x, wv2[it].x, s2); s2 = fmaf(xv.y, wv2[it].y, s2);
                    s2 = fmaf(xv.z, wv2[it].z, s2); s2 = fmaf(xv.w, wv2[it].w, s2);
                    s3 = fmaf(xv.x, wv3[it].x, s3); s3 = fmaf(xv.y, wv3[it].y, s3);
                    s3 = fmaf(xv.z, wv3[it].z, s3); s3 = fmaf(xv.w, wv3[it].w, s3);
                }
                #pragma unroll
                for (int off = 16; off; off >>= 1) {
                    s0 += __shfl_xor_sync(0xffffffffu, s0, off);
                    s1 += __shfl_xor_sync(0xffffffffu, s1, off);
                    s2 += __shfl_xor_sync(0xffffffffu, s2, off);
                    s3 += __shfl_xor_sync(0xffffffffu, s3, off);
                }
                if (lane == 0) g_z[r] = make_float4(s0, s1, s2, s3);
                ++done;
            }
            if (lane == 0 && done) red_release(&g_zcnt[c], (unsigned)done);
        }
    }

    // -------- PHASE 2: broadcast, chunk-by-chunk gated on g_dw --------
    {
        float4* out = a.out;
        const int stride = (a.G - 2) * 256;
        const int self   = wr * 256 + tid;

        for (int c = 0; c < NCH; ++c) {
            if (tid == 0) {
                while (ld_acq(&g_dw[0]) < (unsigned)(c + 1) ||
                       ld_acq(&g_dw[1]) < (unsigned)(c + 1) ||
                       ld_acq(&g_dw[2]) < (unsigned)(c + 1) ||
                       ld_acq(&g_dw[3]) < (unsigned)(c + 1)) __nanosleep(128);
            }
            __syncthreads();
            const int base = c * REG4;
            const int end  = base + REG4;
            #pragma unroll 2
            for (int i = base + self; i < end; i += stride) {
                int row = i >> 7;                       // row = t*128 + b
                float v = g_h[((row & 127) << 8) | (row >> 7)];   // [b][t]
                out[i] = make_float4(v, v, v, v);
            }
        }
        // hx + cx
        const int base = NCH * REG4;   // == ROWS*128
        for (int i = base + self; i < a.n4; i += stride) {
            int row = i >> 7;
            float v;
            if (row < ROWS + BATCH) v = g_h[((row - ROWS) << 8) | 255]; // hx = h[b][255]
            else                    v = g_cfin[row - ROWS - BATCH];     // cx
            out[i] = make_float4(v, v, v, v);
        }
    }
}

// ---------------- launch ----------------
extern "C" void kernel_launch(void* const* d_in, const int* in_sizes, int n_in,
                              void* d_out, int out_size) {
    static int s_sm = -1;
    const int DYN = NBUF * SEQ_T * BATCH * (int)sizeof(float4);   // 64 KB
    if (s_sm < 0) {
        int dev = 0;
        cudaGetDevice(&dev);
        cudaDeviceGetAttribute(&s_sm, cudaDevAttrMultiProcessorCount, dev);
        if (s_sm <= 0) s_sm = 148;
        cudaFuncSetAttribute(fused_kernel,
                             cudaFuncAttributeMaxDynamicSharedMemorySize, DYN);
    }
    const int G  = 2 * s_sm;            // all resident; exactly one sibling vacates
    const int Wp = (G - 2) * 8;

    Args a;
    a.x = (const float*)d_in[0];
    a.W[0] = (const float*)d_in[1];  a.b[0] = (const float*)d_in[2];  a.P[0] = (const float*)d_in[3];
    a.W[1] = (const float*)d_in[4];  a.b[1] = (const float*)d_in[5];  a.P[1] = (const float*)d_in[6];
    a.W[2] = (const float*)d_in[7];  a.b[2] = (const float*)d_in[8];  a.P[2] = (const float*)d_in[9];
    a.W[3] = (const float*)d_in[10]; a.b[3] = (const float*)d_in[11]; a.P[3] = (const float*)d_in[12];
    a.out = (float4*)d_out;
    a.G   = G;
    a.Wp  = Wp;
    a.n4  = out_size / 4;

    init_kernel<<<1, 32>>>();
    fused_kernel<<<G, 256, DYN>>>(a);
}